// round 7
// baseline (speedup 1.0000x reference)
#include <cuda_runtime.h>

// Problem dims
#define BATCH 256
#define SEQ   512
#define DIM   256
#define HID   1024
#define NCLS  10
#define NSTEP 511   // SEQ - 1
#define VOC   512

// -------- device scratch (no allocations allowed) --------
// P[d][v][j]: precomputed input projection per vocab entry.
//   j in [0,HID): g-gate = emb[v]@Wgx_d + bg_d ; j in [HID,2HID): i-gate
__device__ float g_P[2][VOC][2 * HID];        // 8 MB
// h double buffer: [parity][dir][b][j]
__device__ float g_h[2][2][BATCH][HID];       // 4 MB
// cell state (in-place safe: each (d,b,j) owned by exactly one CTA per step)
__device__ float g_c[2][BATCH][HID];          // 2 MB

// -------- f32x2 helpers (FFMA2: 2x fp32 FMA throughput, PTX-only) --------
__device__ __forceinline__ unsigned long long pk2(float lo, float hi) {
    unsigned long long r;
    asm("mov.b64 %0, {%1, %2};" : "=l"(r) : "f"(lo), "f"(hi));
    return r;
}
__device__ __forceinline__ float2 up2(unsigned long long v) {
    float2 f;
    asm("mov.b64 {%0, %1}, %2;" : "=f"(f.x), "=f"(f.y) : "l"(v));
    return f;
}
__device__ __forceinline__ void fma2(unsigned long long& d,
                                     unsigned long long a,
                                     unsigned long long b) {
    asm("fma.rn.f32x2 %0, %1, %2, %0;" : "+l"(d) : "l"(a), "l"(b));
}

__device__ __forceinline__ float sigmoidf_(float x) {
    return 1.0f / (1.0f + __expf(-x));
}

// -------- kernel 1: zero h[parity=0] and c --------
__global__ void zero_state_kernel() {
    int i = blockIdx.x * blockDim.x + threadIdx.x;
    const int N = 2 * BATCH * HID;   // one h parity buffer == size of c
    if (i < N) {
        ((float*)g_h)[i] = 0.0f;     // zeroes g_h[0][...]
        ((float*)g_c)[i] = 0.0f;
    }
}

// -------- kernel 2: precompute P = emb @ [Wgx|Wix] + [bg|bi], both dirs --------
// grid: (VOC/8, 2), block: 256. Each block: 8 vocab rows x all 2048 gate cols.
__global__ void precompute_P_kernel(
    const float* __restrict__ emb,
    const float* __restrict__ Wgx_f, const float* __restrict__ Wix_f,
    const float* __restrict__ bg_f,  const float* __restrict__ bi_f,
    const float* __restrict__ Wgx_b, const float* __restrict__ Wix_b,
    const float* __restrict__ bg_b,  const float* __restrict__ bi_b)
{
    const int d  = blockIdx.y;
    const int v0 = blockIdx.x * 8;
    const float* __restrict__ Wgx = d ? Wgx_b : Wgx_f;
    const float* __restrict__ Wix = d ? Wix_b : Wix_f;
    const float* __restrict__ bg  = d ? bg_b  : bg_f;
    const float* __restrict__ bi  = d ? bi_b  : bi_f;

    __shared__ float es[8][DIM];
    const int tid = threadIdx.x;
    for (int i = tid; i < 8 * DIM; i += 256)
        es[i >> 8][i & 255] = emb[(v0 + (i >> 8)) * DIM + (i & 255)];
    __syncthreads();

    for (int rep = 0; rep < 8; rep++) {
        const int n = tid + rep * 256;            // 0..2047
        const float* __restrict__ W = (n < HID) ? Wgx : Wix;
        const int nn = n & (HID - 1);
        const float bias = (n < HID) ? bg[nn] : bi[nn];
        float acc[8];
        #pragma unroll
        for (int v = 0; v < 8; v++) acc[v] = 0.0f;
        for (int k = 0; k < DIM; k++) {
            const float w = __ldg(&W[k * HID + nn]);
            #pragma unroll
            for (int v = 0; v < 8; v++) acc[v] = fmaf(es[v][k], w, acc[v]);
        }
        #pragma unroll
        for (int v = 0; v < 8; v++) g_P[d][v0 + v][n] = acc[v] + bias;
    }
}

// -------- kernel 3: one LSTM timestep, both directions, fused gates --------
// Per CTA: a 64(batch) x 64(gate-pair) output tile; computes BOTH the g-gate
// GEMM tile (h@Wgh) and i-gate tile (h@Wih) over K=HID, then the elementwise
// LSTM update directly (no scratch round-trip).
// grid: (HID/64, BATCH/64, 2), block: 128 threads (8x16, per-thread 8x4 tile).
#define BM 64
#define BN 64
#define KC 16

__global__ __launch_bounds__(128)
void lstm_step_kernel(
    const int*   __restrict__ x,
    const float* __restrict__ Wgh_f, const float* __restrict__ Wih_f,
    const float* __restrict__ Wgh_b, const float* __restrict__ Wih_b,
    int t)
{
    const int d   = blockIdx.z;
    const int bm0 = blockIdx.y * BM;
    const int bn0 = blockIdx.x * BN;
    const int rp  = t & 1;        // read parity
    const int wp  = rp ^ 1;       // write parity
    const int tid = threadIdx.x;
    const int tn  = tid & 15;
    const int tm  = tid >> 4;
    const int m0  = tm * 8;       // 0..56
    const int n0  = tn * 4;       // 0..60

    const float* __restrict__ Wg  = d ? Wgh_b : Wgh_f;
    const float* __restrict__ Wi  = d ? Wih_b : Wih_f;
    const float* __restrict__ hin = &g_h[rp][d][0][0];

    __shared__ float hsT[KC][BM];   // transposed h tile: [k][m]
    __shared__ float wgs[KC][BN];   // Wgh tile: [k][n]
    __shared__ float wis[KC][BN];   // Wih tile: [k][n]

    unsigned long long aG[8][2], aI[8][2];   // packed f32x2 accumulators
    #pragma unroll
    for (int m = 0; m < 8; m++) {
        aG[m][0] = aG[m][1] = 0ULL;
        aI[m][0] = aI[m][1] = 0ULL;
    }

    for (int kc = 0; kc < HID; kc += KC) {
        // load h tile (transposed into smem)
        #pragma unroll
        for (int i = 0; i < 2; i++) {
            const int idx = tid + i * 128;       // 0..255
            const int m   = idx >> 2;            // 0..63
            const int k4  = (idx & 3) << 2;      // 0,4,8,12
            const float4 v = *(const float4*)&hin[(bm0 + m) * HID + kc + k4];
            hsT[k4 + 0][m] = v.x; hsT[k4 + 1][m] = v.y;
            hsT[k4 + 2][m] = v.z; hsT[k4 + 3][m] = v.w;
        }
        // load weight tiles (coalesced, row-major)
        #pragma unroll
        for (int i = 0; i < 2; i++) {
            const int idx = tid + i * 128;
            const int k   = idx >> 4;            // 0..15
            const int n4  = (idx & 15) << 2;     // 0..60
            *(float4*)&wgs[k][n4] = *(const float4*)&Wg[(kc + k) * HID + bn0 + n4];
            *(float4*)&wis[k][n4] = *(const float4*)&Wi[(kc + k) * HID + bn0 + n4];
        }
        __syncthreads();

        #pragma unroll
        for (int k = 0; k < KC; k++) {
            const float4 a0 = *(const float4*)&hsT[k][m0];
            const float4 a1 = *(const float4*)&hsT[k][m0 + 4];
            const unsigned long long bg01 = *(const unsigned long long*)&wgs[k][n0];
            const unsigned long long bg23 = *(const unsigned long long*)&wgs[k][n0 + 2];
            const unsigned long long bi01 = *(const unsigned long long*)&wis[k][n0];
            const unsigned long long bi23 = *(const unsigned long long*)&wis[k][n0 + 2];
            unsigned long long ad[8];
            ad[0] = pk2(a0.x, a0.x); ad[1] = pk2(a0.y, a0.y);
            ad[2] = pk2(a0.z, a0.z); ad[3] = pk2(a0.w, a0.w);
            ad[4] = pk2(a1.x, a1.x); ad[5] = pk2(a1.y, a1.y);
            ad[6] = pk2(a1.z, a1.z); ad[7] = pk2(a1.w, a1.w);
            #pragma unroll
            for (int m = 0; m < 8; m++) {
                fma2(aG[m][0], ad[m], bg01);
                fma2(aG[m][1], ad[m], bg23);
                fma2(aI[m][0], ad[m], bi01);
                fma2(aI[m][1], ad[m], bi23);
            }
        }
        __syncthreads();
    }

    // Fused LSTM elementwise update.
    // Forward uses token x[b][t]; backward (reversed sequence) uses x[b][SEQ-2-t].
    const int tcol = d ? (SEQ - 2 - t) : t;
    #pragma unroll
    for (int m = 0; m < 8; m++) {
        const int b   = bm0 + m0 + m;
        const int tok = __ldg(&x[b * SEQ + tcol]);
        const float* __restrict__ Pr = &g_P[d][tok][0];
        const int j = bn0 + n0;
        const float4 pg   = *(const float4*)&Pr[j];
        const float4 pi   = *(const float4*)&Pr[HID + j];
        const float2 g01  = up2(aG[m][0]), g23 = up2(aG[m][1]);
        const float2 i01  = up2(aI[m][0]), i23 = up2(aI[m][1]);
        const float4 cold = *(const float4*)&g_c[d][b][j];

        float gv0 = tanhf(g01.x + pg.x);
        float gv1 = tanhf(g01.y + pg.y);
        float gv2 = tanhf(g23.x + pg.z);
        float gv3 = tanhf(g23.y + pg.w);
        float iv0 = sigmoidf_(i01.x + pi.x);
        float iv1 = sigmoidf_(i01.y + pi.y);
        float iv2 = sigmoidf_(i23.x + pi.z);
        float iv3 = sigmoidf_(i23.y + pi.w);

        // source-bug semantics: c = i*(g + c); h = tanh(c)*i
        float c0 = iv0 * (gv0 + cold.x);
        float c1 = iv1 * (gv1 + cold.y);
        float c2 = iv2 * (gv2 + cold.z);
        float c3 = iv3 * (gv3 + cold.w);

        *(float4*)&g_c[d][b][j]     = make_float4(c0, c1, c2, c3);
        *(float4*)&g_h[wp][d][b][j] = make_float4(tanhf(c0) * iv0,
                                                  tanhf(c1) * iv1,
                                                  tanhf(c2) * iv2,
                                                  tanhf(c3) * iv3);
    }
}

// -------- kernel 4: prediction head: out = [hf|hb] @ Wp + bp --------
// Final h lives in parity buffer 1 (last step t=510 is even: reads 0, writes 1).
__global__ void head_kernel(const float* __restrict__ Wp,
                            const float* __restrict__ bp,
                            float* __restrict__ out)
{
    const int b   = blockIdx.x;
    const int tid = threadIdx.x;   // 256
    float acc[NCLS];
    #pragma unroll
    for (int c = 0; c < NCLS; c++) acc[c] = 0.0f;
    for (int j = tid; j < 2 * HID; j += 256) {
        const float hv = (j < HID) ? g_h[1][0][b][j] : g_h[1][1][b][j - HID];
        #pragma unroll
        for (int c = 0; c < NCLS; c++)
            acc[c] = fmaf(hv, __ldg(&Wp[j * NCLS + c]), acc[c]);
    }
    __shared__ float red[8][NCLS];
    #pragma unroll
    for (int c = 0; c < NCLS; c++) {
        float v = acc[c];
        #pragma unroll
        for (int o = 16; o > 0; o >>= 1)
            v += __shfl_down_sync(0xffffffffu, v, o);
        if ((tid & 31) == 0) red[tid >> 5][c] = v;
    }
    __syncthreads();
    if (tid < NCLS) {
        float s = bp[tid];
        #pragma unroll
        for (int w = 0; w < 8; w++) s += red[w][tid];
        out[b * NCLS + tid] = s;
    }
}

extern "C" void kernel_launch(void* const* d_in, const int* in_sizes, int n_in,
                              void* d_out, int out_size) {
    const int*   x     = (const int*)  d_in[0];
    const float* emb   = (const float*)d_in[1];
    const float* Wgx_f = (const float*)d_in[2];
    const float* Wgh_f = (const float*)d_in[3];
    const float* bg_f  = (const float*)d_in[4];
    const float* Wix_f = (const float*)d_in[5];
    const float* Wih_f = (const float*)d_in[6];
    const float* bi_f  = (const float*)d_in[7];
    const float* Wgx_b = (const float*)d_in[8];
    const float* Wgh_b = (const float*)d_in[9];
    const float* bg_b  = (const float*)d_in[10];
    const float* Wix_b = (const float*)d_in[11];
    const float* Wih_b = (const float*)d_in[12];
    const float* bi_b  = (const float*)d_in[13];
    const float* Wp    = (const float*)d_in[14];
    const float* bp    = (const float*)d_in[15];
    float* out = (float*)d_out;

    // re-initialize state every launch (graph replays must be deterministic)
    zero_state_kernel<<<(2 * BATCH * HID + 511) / 512, 512>>>();

    precompute_P_kernel<<<dim3(VOC / 8, 2), 256>>>(
        emb, Wgx_f, Wix_f, bg_f, bi_f, Wgx_b, Wix_b, bg_b, bi_b);

    const dim3 sg(HID / BN, BATCH / BM, 2);   // 16 x 4 x 2 = 128 CTAs
    for (int t = 0; t < NSTEP; t++)
        lstm_step_kernel<<<sg, 128>>>(x, Wgh_f, Wih_f, Wgh_b, Wih_b, t);

    head_kernel<<<BATCH, 256>>>(Wp, bp, out);
}

// round 9
// speedup vs baseline: 3.0264x; 3.0264x over previous
#include <cuda_runtime.h>
#include <cuda_bf16.h>
#include <cstdint>

// Problem dims
#define BATCH 256
#define SEQ   512
#define DIM   256
#define HID   1024
#define NCLS  10
#define NSTEP 511   // SEQ - 1
#define VOC   512

// Step GEMM tiling
#define MT  64            // batch tile
#define NT  64            // j tile (per gate; CTA computes g and i => 128 output cols)
#define KCH 64            // K chunk (64 bf16 = 128 B rows)
#define NCHUNK (HID / KCH)   // 16

// smem stage layout (byte offsets inside one stage)
#define ST_A_HI 0
#define ST_A_LO 8192
#define ST_B_HI 16384
#define ST_B_LO 32768
#define STAGE   49152
#define OPITCH  132          // fp32 O tile row pitch (floats); 132*4=528 B, 16B-divisible

// -------- device scratch (no allocations allowed) --------
__device__ float g_P[2][VOC][2 * HID];                 // input projections, 8 MB
// transposed+split recurrent weights, gates merged on N: n<1024 -> g, n>=1024 -> i
__device__ __nv_bfloat16 g_Wt[2][2][2048][HID];        // [dir][hi/lo][n][k], 16 MB
__device__ __nv_bfloat16 g_hh[2][2][BATCH][HID];       // h high half [parity][dir][b][k]
__device__ __nv_bfloat16 g_hl[2][2][BATCH][HID];       // h low  half
__device__ float g_c[2][BATCH][HID];                   // cell state fp32

// ==================== PTX helpers (baseline sm_80+ features only) ====================
__device__ __forceinline__ uint32_t smem_u32(const void* p) {
    uint32_t a;
    asm("{ .reg .u64 t; cvta.to.shared.u64 t, %1; cvt.u32.u64 %0, t; }" : "=r"(a) : "l"(p));
    return a;
}
__device__ __forceinline__ void cp16(uint32_t saddr, const void* g) {
    asm volatile("cp.async.cg.shared.global [%0], [%1], 16;" :: "r"(saddr), "l"(g) : "memory");
}
#define CP_COMMIT() asm volatile("cp.async.commit_group;" ::: "memory")
#define CP_WAIT1()  asm volatile("cp.async.wait_group 1;" ::: "memory")

__device__ __forceinline__ void ldm4(uint32_t* r, uint32_t addr) {
    asm volatile("ldmatrix.sync.aligned.m8n8.x4.shared.b16 {%0,%1,%2,%3}, [%4];"
                 : "=r"(r[0]), "=r"(r[1]), "=r"(r[2]), "=r"(r[3]) : "r"(addr));
}
// D(16x8,f32) += A(16x16 row-major bf16) * B(16x8 col-major bf16)
__device__ __forceinline__ void mma_bf16(float* c, const uint32_t* a, const uint32_t* b) {
    asm volatile("mma.sync.aligned.m16n8k16.row.col.f32.bf16.bf16.f32 "
                 "{%0,%1,%2,%3}, {%4,%5,%6,%7}, {%8,%9}, {%0,%1,%2,%3};"
                 : "+f"(c[0]), "+f"(c[1]), "+f"(c[2]), "+f"(c[3])
                 : "r"(a[0]), "r"(a[1]), "r"(a[2]), "r"(a[3]), "r"(b[0]), "r"(b[1]));
}
__device__ __forceinline__ float sigmoidf_(float x) { return 1.0f / (1.0f + __expf(-x)); }

// ==================== kernel 1: zero state ====================
__global__ void zero_state_kernel() {
    int i = blockIdx.x * blockDim.x + threadIdx.x;
    const int N = 2 * BATCH * HID;
    if (i < N) {
        ((unsigned short*)g_hh)[i] = 0;   // parity-0 slice
        ((unsigned short*)g_hl)[i] = 0;
        ((float*)g_c)[i] = 0.0f;
    }
}

// ==================== kernel 2: precompute P (verified in R7) ====================
__global__ void precompute_P_kernel(
    const float* __restrict__ emb,
    const float* __restrict__ Wgx_f, const float* __restrict__ Wix_f,
    const float* __restrict__ bg_f,  const float* __restrict__ bi_f,
    const float* __restrict__ Wgx_b, const float* __restrict__ Wix_b,
    const float* __restrict__ bg_b,  const float* __restrict__ bi_b)
{
    const int d  = blockIdx.y;
    const int v0 = blockIdx.x * 8;
    const float* __restrict__ Wgx = d ? Wgx_b : Wgx_f;
    const float* __restrict__ Wix = d ? Wix_b : Wix_f;
    const float* __restrict__ bg  = d ? bg_b  : bg_f;
    const float* __restrict__ bi  = d ? bi_b  : bi_f;

    __shared__ float es[8][DIM];
    const int tid = threadIdx.x;
    for (int i = tid; i < 8 * DIM; i += 256)
        es[i >> 8][i & 255] = emb[(v0 + (i >> 8)) * DIM + (i & 255)];
    __syncthreads();

    for (int rep = 0; rep < 8; rep++) {
        const int n = tid + rep * 256;
        const float* __restrict__ W = (n < HID) ? Wgx : Wix;
        const int nn = n & (HID - 1);
        const float bias = (n < HID) ? bg[nn] : bi[nn];
        float acc[8];
        #pragma unroll
        for (int v = 0; v < 8; v++) acc[v] = 0.0f;
        for (int k = 0; k < DIM; k++) {
            const float w = __ldg(&W[k * HID + nn]);
            #pragma unroll
            for (int v = 0; v < 8; v++) acc[v] = fmaf(es[v][k], w, acc[v]);
        }
        #pragma unroll
        for (int v = 0; v < 8; v++) g_P[d][v0 + v][n] = acc[v] + bias;
    }
}

// ==================== kernel 3: transpose + split weights ====================
// W[k][n] fp32 -> g_Wt[dir][hi/lo][gate*1024+n][k] bf16. grid (32,32,4), block (32,8)
__global__ void transpose_split_kernel(
    const float* __restrict__ W0, const float* __restrict__ W1,
    const float* __restrict__ W2, const float* __restrict__ W3)
{
    const int z = blockIdx.z;                 // 0:Wgh_f 1:Wih_f 2:Wgh_b 3:Wih_b
    const float* __restrict__ W = (z == 0) ? W0 : (z == 1) ? W1 : (z == 2) ? W2 : W3;
    const int d = z >> 1, gate = z & 1;
    const int k0 = blockIdx.x * 32, n0 = blockIdx.y * 32;
    const int tx = threadIdx.x, ty = threadIdx.y;

    __shared__ float ts[32][33];
    #pragma unroll
    for (int i = 0; i < 4; i++)
        ts[ty + i * 8][tx] = W[(k0 + ty + i * 8) * HID + n0 + tx];
    __syncthreads();
    #pragma unroll
    for (int i = 0; i < 4; i++) {
        const float v = ts[tx][ty + i * 8];
        const __nv_bfloat16 hi = __float2bfloat16_rn(v);
        const __nv_bfloat16 lo = __float2bfloat16_rn(v - __bfloat162float(hi));
        const int n = gate * HID + n0 + ty + i * 8;
        g_Wt[d][0][n][k0 + tx] = hi;
        g_Wt[d][1][n][k0 + tx] = lo;
    }
}

// ==================== kernel 4: HMMA LSTM step ====================
// grid (16 j, 4 m, 2 dir) = 128 CTAs, 256 threads (8 warps, 2m x 4n of 32x32 tiles).
// Output per CTA: O[64 batch][128] = [g-gate cols j0..j0+63 | i-gate cols].
// 3-term split-bf16 (hi*hi + lo*hi + hi*lo), fp32 register accumulators.
__global__ __launch_bounds__(256, 1)
void lstm_step_mma(const int* __restrict__ x, int t)
{
    extern __shared__ char sm_raw[];
    char* smp = (char*)(((uintptr_t)sm_raw + 1023) & ~(uintptr_t)1023);
    const uint32_t smb = smem_u32(smp);

    const int d   = blockIdx.z;
    const int bm0 = blockIdx.y * MT;
    const int j0  = blockIdx.x * NT;
    const int rp  = t & 1;
    const int wp  = rp ^ 1;
    const int tid = threadIdx.x;
    const int wid = tid >> 5, lane = tid & 31;
    const int wm = wid >> 2, wn = wid & 3;       // warp grid 2m x 4n

    const char* srcA0 = (const char*)&g_hh[rp][d][bm0][0];
    const char* srcA1 = (const char*)&g_hl[rp][d][bm0][0];
    const char* srcB0 = (const char*)&g_Wt[d][0][0][0];
    const char* srcB1 = (const char*)&g_Wt[d][1][0][0];

    // ---- chunk loader: 48 KB per stage via cp.async (12 x 16B per thread) ----
    auto load_chunk = [&](int c, int sb) {
        const int kb = c * 128;                  // byte offset along k
        #pragma unroll
        for (int i = 0; i < 4; i++) {            // A hi/lo: 2 x 64 rows x 128 B
            const int idx = tid + i * 256;
            const int hl = idx >> 9, r = (idx >> 3) & 63, ch = idx & 7;
            const uint32_t sa = smb + sb + (hl ? ST_A_LO : ST_A_HI)
                              + r * 128 + ((ch ^ (r & 7)) << 4);
            const char* g = (hl ? srcA1 : srcA0) + r * 2048 + kb + ch * 16;
            cp16(sa, g);
        }
        #pragma unroll
        for (int i = 0; i < 8; i++) {            // B hi/lo: 2 x 128 rows x 128 B
            const int idx = tid + i * 256;
            const int hl = idx >> 10, br = (idx >> 3) & 127, ch = idx & 7;
            const int n = j0 + br + ((br & 64) ? 960 : 0);   // g rows then i rows
            const uint32_t sa = smb + sb + (hl ? ST_B_LO : ST_B_HI)
                              + br * 128 + ((ch ^ (br & 7)) << 4);
            const char* g = (hl ? srcB1 : srcB0) + (size_t)n * 2048 + kb + ch * 16;
            cp16(sa, g);
        }
    };

    float acc[2][4][4];
    #pragma unroll
    for (int mi = 0; mi < 2; mi++)
        #pragma unroll
        for (int ni = 0; ni < 4; ni++)
            #pragma unroll
            for (int e = 0; e < 4; e++) acc[mi][ni][e] = 0.0f;

    load_chunk(0, 0);     CP_COMMIT();
    load_chunk(1, STAGE); CP_COMMIT();

    for (int c = 0; c < NCHUNK; c++) {
        CP_WAIT1();
        __syncthreads();
        const uint32_t buf = smb + (c & 1) * STAGE;

        #pragma unroll
        for (int s = 0; s < 4; s++) {            // 4 k16 steps per chunk
            uint32_t ah[2][4], al[2][4], bh[2][4], bl[2][4];
            #pragma unroll
            for (int mi = 0; mi < 2; mi++) {
                const int row = wm * 32 + mi * 16 + (lane & 15);
                const int cg  = s * 2 + (lane >> 4);
                const uint32_t a = buf + ST_A_HI + row * 128 + ((cg ^ (row & 7)) << 4);
                ldm4(ah[mi], a);
                ldm4(al[mi], a + (ST_A_LO - ST_A_HI));
            }
            #pragma unroll
            for (int p = 0; p < 2; p++) {        // each x4 covers two 8-col n-tiles
                const int br = wn * 32 + p * 16 + ((lane >> 4) << 3) + (lane & 7);
                const int cg = s * 2 + ((lane >> 3) & 1);
                const uint32_t a = buf + ST_B_HI + br * 128 + ((cg ^ (br & 7)) << 4);
                ldm4(bh[p], a);
                ldm4(bl[p], a + (ST_B_LO - ST_B_HI));
            }
            #pragma unroll
            for (int mi = 0; mi < 2; mi++)
                #pragma unroll
                for (int ni = 0; ni < 4; ni++) {
                    const uint32_t* bhp = &bh[ni >> 1][(ni & 1) * 2];
                    const uint32_t* blp = &bl[ni >> 1][(ni & 1) * 2];
                    mma_bf16(acc[mi][ni], ah[mi], bhp);   // hi*hi
                    mma_bf16(acc[mi][ni], al[mi], bhp);   // lo*hi
                    mma_bf16(acc[mi][ni], ah[mi], blp);   // hi*lo
                }
        }
        __syncthreads();
        if (c + 2 < NCHUNK) load_chunk(c + 2, (c & 1) * STAGE);
        CP_COMMIT();                              // empty groups keep wait counts aligned
    }

    // ---- stage accumulators through smem so g and i pair up per (b, j) ----
    float* O = (float*)smp;                       // 64 x OPITCH fp32 (overwrites stage 0)
    #pragma unroll
    for (int mi = 0; mi < 2; mi++)
        #pragma unroll
        for (int ni = 0; ni < 4; ni++) {
            const int r0  = wm * 32 + mi * 16 + (lane >> 2);
            const int col = wn * 32 + ni * 8 + (lane & 3) * 2;
            *(float2*)&O[r0 * OPITCH + col]       = make_float2(acc[mi][ni][0], acc[mi][ni][1]);
            *(float2*)&O[(r0 + 8) * OPITCH + col] = make_float2(acc[mi][ni][2], acc[mi][ni][3]);
        }
    __syncthreads();

    // ---- fused LSTM elementwise update (same math as the passing R7 kernel) ----
    const int tcol = d ? (SEQ - 2 - t) : t;
    #pragma unroll
    for (int rep = 0; rep < 4; rep++) {
        const int qid = tid + rep * 256;          // 1024 j-quads: 64 b x 16 quads
        const int bl_ = qid >> 4;
        const int jl  = (qid & 15) * 4;
        const int b   = bm0 + bl_;
        const int tok = __ldg(&x[b * SEQ + tcol]);
        const int j   = j0 + jl;

        const float4 ga = *(const float4*)&O[bl_ * OPITCH + jl];
        const float4 ia = *(const float4*)&O[bl_ * OPITCH + 64 + jl];
        const float4 pg = *(const float4*)&g_P[d][tok][j];
        const float4 pi = *(const float4*)&g_P[d][tok][HID + j];
        const float4 co = *(const float4*)&g_c[d][b][j];

        float gv[4], iv[4], cn[4], hn[4];
        gv[0] = tanhf(ga.x + pg.x); gv[1] = tanhf(ga.y + pg.y);
        gv[2] = tanhf(ga.z + pg.z); gv[3] = tanhf(ga.w + pg.w);
        iv[0] = sigmoidf_(ia.x + pi.x); iv[1] = sigmoidf_(ia.y + pi.y);
        iv[2] = sigmoidf_(ia.z + pi.z); iv[3] = sigmoidf_(ia.w + pi.w);

        cn[0] = iv[0] * (gv[0] + co.x);
        cn[1] = iv[1] * (gv[1] + co.y);
        cn[2] = iv[2] * (gv[2] + co.z);
        cn[3] = iv[3] * (gv[3] + co.w);
        *(float4*)&g_c[d][b][j] = make_float4(cn[0], cn[1], cn[2], cn[3]);

        #pragma unroll
        for (int e = 0; e < 4; e++) hn[e] = tanhf(cn[e]) * iv[e];

        __nv_bfloat16 h0 = __float2bfloat16_rn(hn[0]);
        __nv_bfloat16 h1 = __float2bfloat16_rn(hn[1]);
        __nv_bfloat16 h2 = __float2bfloat16_rn(hn[2]);
        __nv_bfloat16 h3 = __float2bfloat16_rn(hn[3]);
        __nv_bfloat162 p01 = __halves2bfloat162(h0, h1);
        __nv_bfloat162 p23 = __halves2bfloat162(h2, h3);
        *(uint32_t*)&g_hh[wp][d][b][j]     = *(uint32_t*)&p01;
        *(uint32_t*)&g_hh[wp][d][b][j + 2] = *(uint32_t*)&p23;
        __nv_bfloat162 l01 = __halves2bfloat162(
            __float2bfloat16_rn(hn[0] - __bfloat162float(h0)),
            __float2bfloat16_rn(hn[1] - __bfloat162float(h1)));
        __nv_bfloat162 l23 = __halves2bfloat162(
            __float2bfloat16_rn(hn[2] - __bfloat162float(h2)),
            __float2bfloat16_rn(hn[3] - __bfloat162float(h3)));
        *(uint32_t*)&g_hl[wp][d][b][j]     = *(uint32_t*)&l01;
        *(uint32_t*)&g_hl[wp][d][b][j + 2] = *(uint32_t*)&l23;
    }
}

// ==================== kernel 5: prediction head ====================
// Final h is in parity 1 (t=510 even: reads 0, writes 1). h = hi + lo.
__global__ void head_kernel(const float* __restrict__ Wp,
                            const float* __restrict__ bp,
                            float* __restrict__ out)
{
    const int b   = blockIdx.x;
    const int tid = threadIdx.x;   // 256
    float acc[NCLS];
    #pragma unroll
    for (int c = 0; c < NCLS; c++) acc[c] = 0.0f;
    for (int j = tid; j < 2 * HID; j += 256) {
        const int dd = (j < HID) ? 0 : 1;
        const int jj = j & (HID - 1);
        const float hv = __bfloat162float(g_hh[1][dd][b][jj]) +
                         __bfloat162float(g_hl[1][dd][b][jj]);
        #pragma unroll
        for (int c = 0; c < NCLS; c++)
            acc[c] = fmaf(hv, __ldg(&Wp[j * NCLS + c]), acc[c]);
    }
    __shared__ float red[8][NCLS];
    #pragma unroll
    for (int c = 0; c < NCLS; c++) {
        float v = acc[c];
        #pragma unroll
        for (int o = 16; o > 0; o >>= 1)
            v += __shfl_down_sync(0xffffffffu, v, o);
        if ((tid & 31) == 0) red[tid >> 5][c] = v;
    }
    __syncthreads();
    if (tid < NCLS) {
        float s = bp[tid];
        #pragma unroll
        for (int w = 0; w < 8; w++) s += red[w][tid];
        out[b * NCLS + tid] = s;
    }
}

// ==================== launch ====================
extern "C" void kernel_launch(void* const* d_in, const int* in_sizes, int n_in,
                              void* d_out, int out_size) {
    const int*   x     = (const int*)  d_in[0];
    const float* emb   = (const float*)d_in[1];
    const float* Wgx_f = (const float*)d_in[2];
    const float* Wgh_f = (const float*)d_in[3];
    const float* bg_f  = (const float*)d_in[4];
    const float* Wix_f = (const float*)d_in[5];
    const float* Wih_f = (const float*)d_in[6];
    const float* bi_f  = (const float*)d_in[7];
    const float* Wgx_b = (const float*)d_in[8];
    const float* Wgh_b = (const float*)d_in[9];
    const float* bg_b  = (const float*)d_in[10];
    const float* Wix_b = (const float*)d_in[11];
    const float* Wih_b = (const float*)d_in[12];
    const float* bi_b  = (const float*)d_in[13];
    const float* Wp    = (const float*)d_in[14];
    const float* bp    = (const float*)d_in[15];
    float* out = (float*)d_out;

    const int DSMEM = 2 * STAGE + 1024;   // 98 KB stages + alignment slack
    cudaFuncSetAttribute(lstm_step_mma, cudaFuncAttributeMaxDynamicSharedMemorySize, DSMEM);

    zero_state_kernel<<<(2 * BATCH * HID + 511) / 512, 512>>>();
    precompute_P_kernel<<<dim3(VOC / 8, 2), 256>>>(
        emb, Wgx_f, Wix_f, bg_f, bi_f, Wgx_b, Wix_b, bg_b, bi_b);
    transpose_split_kernel<<<dim3(32, 32, 4), dim3(32, 8)>>>(Wgh_f, Wih_f, Wgh_b, Wih_b);

    const dim3 sg(HID / NT, BATCH / MT, 2);   // 16 x 4 x 2 = 128 CTAs
    for (int t = 0; t < NSTEP; t++)
        lstm_step_mma<<<sg, 256, DSMEM>>>(x, t);

    head_kernel<<<BATCH, 256>>>(Wp, bp, out);
}